// round 11
// baseline (speedup 1.0000x reference)
#include <cuda_runtime.h>
#include <math.h>

// Problem constants
#define NG    2048
#define HH    128
#define WW    128
#define NPIX  (HH*WW)
#define NSEG  8
#define SEG_LEN (NG/NSEG)   // 256

// ---------------- scratch (__device__ globals; no allocation allowed) -------
__device__ float  g_attr[NG][10];      // u,v,hA,B,hC,opa_m,r,g,b,key
__device__ float4 g_rec0[NG];          // u, v, hA(=-0.5A), hC(=-0.5C)
__device__ float4 g_rec1[NG];          // B, opa, r, g
__device__ float  g_recb[NG];          // b
__device__ float4 g_seg[NSEG * NPIX];  // per-(segment,pixel): cr,cg,cb,T

// ---------------------------------------------------------------------------
// Kernel 1: per-gaussian preprocessing
// ---------------------------------------------------------------------------
__global__ void prep_kernel(const float* __restrict__ pos,
                            const float* __restrict__ rgb,
                            const float* __restrict__ opa,
                            const float* __restrict__ quat,
                            const float* __restrict__ scale,
                            const float* __restrict__ wq,
                            const float* __restrict__ wt)
{
    int n = blockIdx.x * blockDim.x + threadIdx.x;
    if (n >= NG) return;

    // world->camera rotation from quaternion (normalized with +1e-12)
    float qw = wq[0], qx = wq[1], qy = wq[2], qz = wq[3];
    float qn = sqrtf(qw*qw + qx*qx + qy*qy + qz*qz) + 1e-12f;
    qw /= qn; qx /= qn; qy /= qn; qz /= qn;
    float r00 = 1.f - 2.f*(qy*qy + qz*qz), r01 = 2.f*(qx*qy - qw*qz), r02 = 2.f*(qx*qz + qw*qy);
    float r10 = 2.f*(qx*qy + qw*qz), r11 = 1.f - 2.f*(qx*qx + qz*qz), r12 = 2.f*(qy*qz - qw*qx);
    float r20 = 2.f*(qx*qz - qw*qy), r21 = 2.f*(qy*qz + qw*qx), r22 = 1.f - 2.f*(qx*qx + qy*qy);

    float p0 = pos[n*3+0], p1 = pos[n*3+1], p2 = pos[n*3+2];
    float x = r00*p0 + r01*p1 + r02*p2 + wt[0];
    float y = r10*p0 + r11*p1 + r12*p2 + wt[1];
    float z = r20*p0 + r21*p1 + r22*p2 + wt[2];

    float dnorm = sqrtf(x*x + y*y + z*z);
    bool  mask  = z > 1.1f;
    float zs    = mask ? z : 1.0f;
    float u     = x / zs;
    float v     = y / zs;
    mask = mask && (fabsf(u) < 0.64f) && (fabsf(v) < 0.64f);

    float iz   = 1.0f / zs;
    float iz2  = iz * iz;
    float inrm = 1.0f / fmaxf(dnorm, 1e-8f);
    (void)inrm; // third J row doesn't enter the 2x2 block

    // rows 0,1 of JW = J @ rot
    float xz2 = x * iz2, yz2 = y * iz2;
    float jw00 = iz*r00 - xz2*r20, jw01 = iz*r01 - xz2*r21, jw02 = iz*r02 - xz2*r22;
    float jw10 = iz*r10 - yz2*r20, jw11 = iz*r11 - yz2*r21, jw12 = iz*r12 - yz2*r22;

    // gaussian rotation
    float gw = quat[n*4+0], gx = quat[n*4+1], gy = quat[n*4+2], gz = quat[n*4+3];
    float gn = sqrtf(gw*gw + gx*gx + gy*gy + gz*gz) + 1e-12f;
    gw /= gn; gx /= gn; gy /= gn; gz /= gn;
    float g00 = 1.f - 2.f*(gy*gy + gz*gz), g01 = 2.f*(gx*gy - gw*gz), g02 = 2.f*(gx*gz + gw*gy);
    float g10 = 2.f*(gx*gy + gw*gz), g11 = 1.f - 2.f*(gx*gx + gz*gz), g12 = 2.f*(gy*gz - gw*gx);
    float g20 = 2.f*(gx*gz - gw*gy), g21 = 2.f*(gy*gz + gw*gx), g22 = 1.f - 2.f*(gx*gx + gy*gy);

    float sx = scale[n*3+0], sy = scale[n*3+1], sz = scale[n*3+2];
    // RS[i][j] = Rg[i][j] * s_j
    float a00 = g00*sx, a01 = g01*sy, a02 = g02*sz;
    float a10 = g10*sx, a11 = g11*sy, a12 = g12*sz;
    float a20 = g20*sx, a21 = g21*sy, a22 = g22*sz;

    // cov3d = RS RS^T (symmetric)
    float c00 = a00*a00 + a01*a01 + a02*a02;
    float c01 = a00*a10 + a01*a11 + a02*a12;
    float c02 = a00*a20 + a01*a21 + a02*a22;
    float c11 = a10*a10 + a11*a11 + a12*a12;
    float c12 = a10*a20 + a11*a21 + a12*a22;
    float c22 = a20*a20 + a21*a21 + a22*a22;

    // t0 = cov3d @ jw0, t1 = cov3d @ jw1
    float t00 = c00*jw00 + c01*jw01 + c02*jw02;
    float t01 = c01*jw00 + c11*jw01 + c12*jw02;
    float t02 = c02*jw00 + c12*jw01 + c22*jw02;
    float t10 = c00*jw10 + c01*jw11 + c02*jw12;
    float t11 = c01*jw10 + c11*jw11 + c12*jw12;
    float t12 = c02*jw10 + c12*jw11 + c22*jw12;

    float a = jw00*t00 + jw01*t01 + jw02*t02 + 1e-6f;
    float b = jw00*t10 + jw01*t11 + jw02*t12;
    float c = jw10*t10 + jw11*t11 + jw12*t12 + 1e-6f;

    float inv_det = 1.0f / fmaxf(a*c - b*b, 1e-12f);
    float A = c * inv_det;
    float B = b * inv_det;
    float C = a * inv_det;

    g_attr[n][0] = u;
    g_attr[n][1] = v;
    g_attr[n][2] = -0.5f * A;
    g_attr[n][3] = B;
    g_attr[n][4] = -0.5f * C;
    g_attr[n][5] = mask ? opa[n] : 0.0f;
    g_attr[n][6] = rgb[n*3+0];
    g_attr[n][7] = rgb[n*3+1];
    g_attr[n][8] = rgb[n*3+2];
    g_attr[n][9] = mask ? dnorm : INFINITY;
}

// ---------------------------------------------------------------------------
// Kernel 2: bitonic sort by depth (idx tie-break = stable) + gather
// ---------------------------------------------------------------------------
__global__ void sort_kernel()
{
    __shared__ float sk[NG];
    __shared__ int   si[NG];
    int tid = threadIdx.x;  // 1024 threads

    for (int e = tid; e < NG; e += 1024) { sk[e] = g_attr[e][9]; si[e] = e; }

    for (int k = 2; k <= NG; k <<= 1) {
        for (int j = k >> 1; j > 0; j >>= 1) {
            __syncthreads();
            for (int e = tid; e < NG; e += 1024) {
                int ixj = e ^ j;
                if (ixj > e) {
                    float ka = sk[e], kb = sk[ixj];
                    int   ia = si[e], ib = si[ixj];
                    bool up = ((e & k) == 0);
                    bool gt = (ka > kb) || (ka == kb && ia > ib);
                    if (gt == up) {
                        sk[e] = kb; sk[ixj] = ka;
                        si[e] = ib; si[ixj] = ia;
                    }
                }
            }
        }
    }
    __syncthreads();

    for (int e = tid; e < NG; e += 1024) {
        int s = si[e];
        g_rec0[e] = make_float4(g_attr[s][0], g_attr[s][1], g_attr[s][2], g_attr[s][4]);
        g_rec1[e] = make_float4(g_attr[s][3], g_attr[s][5], g_attr[s][6], g_attr[s][7]);
        g_recb[e] = g_attr[s][8];
    }
}

// ---------------------------------------------------------------------------
// Kernel 3: segmented alpha-blend render
// grid = (64 tiles of 16x16, NSEG), block = 256
// ---------------------------------------------------------------------------
__global__ __launch_bounds__(SEG_LEN, 4)
void render_kernel()
{
    __shared__ float4 s0[SEG_LEN];
    __shared__ float4 s1[SEG_LEN];
    __shared__ float  sb[SEG_LEN];

    int tid  = threadIdx.x;
    int seg  = blockIdx.y;
    int base = seg * SEG_LEN;

    s0[tid] = g_rec0[base + tid];
    s1[tid] = g_rec1[base + tid];
    sb[tid] = g_recb[base + tid];
    __syncthreads();

    int tileX = blockIdx.x & 7;
    int tileY = blockIdx.x >> 3;
    int px = tileX * 16 + (tid & 15);
    int py = tileY * 16 + (tid >> 4);
    float pu = (px + 0.5f - 64.0f) / 100.0f;
    float pv = (py + 0.5f - 64.0f) / 100.0f;

    float T = 1.0f, cr = 0.0f, cg = 0.0f, cb = 0.0f;

    #pragma unroll 4
    for (int g = 0; g < SEG_LEN; g++) {
        float4 a  = s0[g];
        float dx  = pu - a.x;
        float dy  = pv - a.y;
        float dx2 = dx * dx, dy2 = dy * dy, dxy = dx * dy;
        float4 bq = s1[g];
        float power = a.z * dx2 + a.w * dy2 + bq.x * dxy;
        // warp-uniform skip: exp(-18) ~ 1.5e-8, total abs error <= ~3e-5
        if (__any_sync(0xffffffffu, power > -18.0f)) {
            float al = fminf(bq.y * __expf(fminf(power, 0.0f)), 0.99f);
            float w  = T * al;
            cr = fmaf(w, bq.z, cr);
            cg = fmaf(w, bq.w, cg);
            cb = fmaf(w, sb[g], cb);
            T -= w;
        }
    }

    g_seg[seg * NPIX + py * WW + px] = make_float4(cr, cg, cb, T);
}

// ---------------------------------------------------------------------------
// Kernel 4: combine segment partials: img = sum_s (prod_{t<s} P_t) * C_s
// ---------------------------------------------------------------------------
__global__ void combine_kernel(float* __restrict__ out)
{
    int p = blockIdx.x * blockDim.x + threadIdx.x;
    if (p >= NPIX) return;
    float T = 1.0f, cr = 0.0f, cg = 0.0f, cb = 0.0f;
    #pragma unroll
    for (int s = 0; s < NSEG; s++) {
        float4 v = g_seg[s * NPIX + p];
        cr = fmaf(T, v.x, cr);
        cg = fmaf(T, v.y, cg);
        cb = fmaf(T, v.z, cb);
        T *= v.w;
    }
    out[p*3 + 0] = cr;
    out[p*3 + 1] = cg;
    out[p*3 + 2] = cb;
}

// ---------------------------------------------------------------------------
extern "C" void kernel_launch(void* const* d_in, const int* in_sizes, int n_in,
                              void* d_out, int out_size)
{
    const float* pos   = (const float*)d_in[0];
    const float* rgb   = (const float*)d_in[1];
    const float* opa   = (const float*)d_in[2];
    const float* quat  = (const float*)d_in[3];
    const float* scale = (const float*)d_in[4];
    const float* wq    = (const float*)d_in[5];
    const float* wt    = (const float*)d_in[6];
    float* out = (float*)d_out;

    prep_kernel<<<NG/256, 256>>>(pos, rgb, opa, quat, scale, wq, wt);
    sort_kernel<<<1, 1024>>>();
    render_kernel<<<dim3(64, NSEG), SEG_LEN>>>();
    combine_kernel<<<NPIX/256, 256>>>(out);
}

// round 12
// speedup vs baseline: 1.0063x; 1.0063x over previous
#include <cuda_runtime.h>
#include <math.h>

// Problem constants
#define NG    2048
#define HH    128
#define WW    128
#define NPIX  (HH*WW)
#define NSEG  8
#define SEG_LEN (NG/NSEG)   // 256

// ---------------- scratch (__device__ globals; no allocation allowed) -------
__device__ float  g_attr[NG][10];      // u,v,hA,B,hC,opa_m,r,g,b,key
__device__ float4 g_rec0[NG];          // u, v, hA(=-0.5A), hC(=-0.5C)
__device__ float4 g_rec1[NG];          // B, opa, r, g
__device__ float  g_recb[NG];          // b
__device__ float4 g_seg[NSEG * NPIX];  // per-(segment,pixel): cr,cg,cb,T

// ---------------------------------------------------------------------------
// Kernel 1: per-gaussian preprocessing
// ---------------------------------------------------------------------------
__global__ void prep_kernel(const float* __restrict__ pos,
                            const float* __restrict__ rgb,
                            const float* __restrict__ opa,
                            const float* __restrict__ quat,
                            const float* __restrict__ scale,
                            const float* __restrict__ wq,
                            const float* __restrict__ wt)
{
    int n = blockIdx.x * blockDim.x + threadIdx.x;
    if (n >= NG) return;

    // world->camera rotation from quaternion (normalized with +1e-12)
    float qw = wq[0], qx = wq[1], qy = wq[2], qz = wq[3];
    float qn = sqrtf(qw*qw + qx*qx + qy*qy + qz*qz) + 1e-12f;
    qw /= qn; qx /= qn; qy /= qn; qz /= qn;
    float r00 = 1.f - 2.f*(qy*qy + qz*qz), r01 = 2.f*(qx*qy - qw*qz), r02 = 2.f*(qx*qz + qw*qy);
    float r10 = 2.f*(qx*qy + qw*qz), r11 = 1.f - 2.f*(qx*qx + qz*qz), r12 = 2.f*(qy*qz - qw*qx);
    float r20 = 2.f*(qx*qz - qw*qy), r21 = 2.f*(qy*qz + qw*qx), r22 = 1.f - 2.f*(qx*qx + qy*qy);

    float p0 = pos[n*3+0], p1 = pos[n*3+1], p2 = pos[n*3+2];
    float x = r00*p0 + r01*p1 + r02*p2 + wt[0];
    float y = r10*p0 + r11*p1 + r12*p2 + wt[1];
    float z = r20*p0 + r21*p1 + r22*p2 + wt[2];

    float dnorm = sqrtf(x*x + y*y + z*z);
    bool  mask  = z > 1.1f;
    float zs    = mask ? z : 1.0f;
    float u     = x / zs;
    float v     = y / zs;
    mask = mask && (fabsf(u) < 0.64f) && (fabsf(v) < 0.64f);

    float iz   = 1.0f / zs;
    float iz2  = iz * iz;
    float inrm = 1.0f / fmaxf(dnorm, 1e-8f);
    (void)inrm; // third J row doesn't enter the 2x2 block

    // rows 0,1 of JW = J @ rot
    float xz2 = x * iz2, yz2 = y * iz2;
    float jw00 = iz*r00 - xz2*r20, jw01 = iz*r01 - xz2*r21, jw02 = iz*r02 - xz2*r22;
    float jw10 = iz*r10 - yz2*r20, jw11 = iz*r11 - yz2*r21, jw12 = iz*r12 - yz2*r22;

    // gaussian rotation
    float gw = quat[n*4+0], gx = quat[n*4+1], gy = quat[n*4+2], gz = quat[n*4+3];
    float gn = sqrtf(gw*gw + gx*gx + gy*gy + gz*gz) + 1e-12f;
    gw /= gn; gx /= gn; gy /= gn; gz /= gn;
    float g00 = 1.f - 2.f*(gy*gy + gz*gz), g01 = 2.f*(gx*gy - gw*gz), g02 = 2.f*(gx*gz + gw*gy);
    float g10 = 2.f*(gx*gy + gw*gz), g11 = 1.f - 2.f*(gx*gx + gz*gz), g12 = 2.f*(gy*gz - gw*gx);
    float g20 = 2.f*(gx*gz - gw*gy), g21 = 2.f*(gy*gz + gw*gx), g22 = 1.f - 2.f*(gx*gx + gy*gy);

    float sx = scale[n*3+0], sy = scale[n*3+1], sz = scale[n*3+2];
    // RS[i][j] = Rg[i][j] * s_j
    float a00 = g00*sx, a01 = g01*sy, a02 = g02*sz;
    float a10 = g10*sx, a11 = g11*sy, a12 = g12*sz;
    float a20 = g20*sx, a21 = g21*sy, a22 = g22*sz;

    // cov3d = RS RS^T (symmetric)
    float c00 = a00*a00 + a01*a01 + a02*a02;
    float c01 = a00*a10 + a01*a11 + a02*a12;
    float c02 = a00*a20 + a01*a21 + a02*a22;
    float c11 = a10*a10 + a11*a11 + a12*a12;
    float c12 = a10*a20 + a11*a21 + a12*a22;
    float c22 = a20*a20 + a21*a21 + a22*a22;

    // t0 = cov3d @ jw0, t1 = cov3d @ jw1
    float t00 = c00*jw00 + c01*jw01 + c02*jw02;
    float t01 = c01*jw00 + c11*jw01 + c12*jw02;
    float t02 = c02*jw00 + c12*jw01 + c22*jw02;
    float t10 = c00*jw10 + c01*jw11 + c02*jw12;
    float t11 = c01*jw10 + c11*jw11 + c12*jw12;
    float t12 = c02*jw10 + c12*jw11 + c22*jw12;

    float a = jw00*t00 + jw01*t01 + jw02*t02 + 1e-6f;
    float b = jw00*t10 + jw01*t11 + jw02*t12;
    float c = jw10*t10 + jw11*t11 + jw12*t12 + 1e-6f;

    float inv_det = 1.0f / fmaxf(a*c - b*b, 1e-12f);
    float A = c * inv_det;
    float B = b * inv_det;
    float C = a * inv_det;

    g_attr[n][0] = u;
    g_attr[n][1] = v;
    g_attr[n][2] = -0.5f * A;
    g_attr[n][3] = B;
    g_attr[n][4] = -0.5f * C;
    g_attr[n][5] = mask ? opa[n] : 0.0f;
    g_attr[n][6] = rgb[n*3+0];
    g_attr[n][7] = rgb[n*3+1];
    g_attr[n][8] = rgb[n*3+2];
    g_attr[n][9] = mask ? dnorm : INFINITY;
}

// ---------------------------------------------------------------------------
// Kernel 2: bitonic sort by depth (idx tie-break = stable) + gather
// ---------------------------------------------------------------------------
__global__ void sort_kernel()
{
    __shared__ float sk[NG];
    __shared__ int   si[NG];
    int tid = threadIdx.x;  // 1024 threads

    for (int e = tid; e < NG; e += 1024) { sk[e] = g_attr[e][9]; si[e] = e; }

    for (int k = 2; k <= NG; k <<= 1) {
        for (int j = k >> 1; j > 0; j >>= 1) {
            __syncthreads();
            for (int e = tid; e < NG; e += 1024) {
                int ixj = e ^ j;
                if (ixj > e) {
                    float ka = sk[e], kb = sk[ixj];
                    int   ia = si[e], ib = si[ixj];
                    bool up = ((e & k) == 0);
                    bool gt = (ka > kb) || (ka == kb && ia > ib);
                    if (gt == up) {
                        sk[e] = kb; sk[ixj] = ka;
                        si[e] = ib; si[ixj] = ia;
                    }
                }
            }
        }
    }
    __syncthreads();

    for (int e = tid; e < NG; e += 1024) {
        int s = si[e];
        g_rec0[e] = make_float4(g_attr[s][0], g_attr[s][1], g_attr[s][2], g_attr[s][4]);
        g_rec1[e] = make_float4(g_attr[s][3], g_attr[s][5], g_attr[s][6], g_attr[s][7]);
        g_recb[e] = g_attr[s][8];
    }
}

// ---------------------------------------------------------------------------
// Kernel 3: segmented alpha-blend render
// grid = (64 tiles of 16x16, NSEG), block = 256
// ---------------------------------------------------------------------------
__global__ __launch_bounds__(SEG_LEN, 4)
void render_kernel()
{
    __shared__ float4 s0[SEG_LEN];
    __shared__ float4 s1[SEG_LEN];
    __shared__ float  sb[SEG_LEN];

    int tid  = threadIdx.x;
    int seg  = blockIdx.y;
    int base = seg * SEG_LEN;

    s0[tid] = g_rec0[base + tid];
    s1[tid] = g_rec1[base + tid];
    sb[tid] = g_recb[base + tid];
    __syncthreads();

    int tileX = blockIdx.x & 7;
    int tileY = blockIdx.x >> 3;
    int px = tileX * 16 + (tid & 15);
    int py = tileY * 16 + (tid >> 4);
    float pu = (px + 0.5f - 64.0f) / 100.0f;
    float pv = (py + 0.5f - 64.0f) / 100.0f;

    float T = 1.0f, cr = 0.0f, cg = 0.0f, cb = 0.0f;

    #pragma unroll 4
    for (int g = 0; g < SEG_LEN; g++) {
        float4 a  = s0[g];
        float dx  = pu - a.x;
        float dy  = pv - a.y;
        float dx2 = dx * dx, dy2 = dy * dy, dxy = dx * dy;
        float4 bq = s1[g];
        float power = a.z * dx2 + a.w * dy2 + bq.x * dxy;
        // warp-uniform skip: exp(-18) ~ 1.5e-8, total abs error <= ~3e-5
        if (__any_sync(0xffffffffu, power > -18.0f)) {
            float al = fminf(bq.y * __expf(fminf(power, 0.0f)), 0.99f);
            float w  = T * al;
            cr = fmaf(w, bq.z, cr);
            cg = fmaf(w, bq.w, cg);
            cb = fmaf(w, sb[g], cb);
            T -= w;
        }
    }

    g_seg[seg * NPIX + py * WW + px] = make_float4(cr, cg, cb, T);
}

// ---------------------------------------------------------------------------
// Kernel 4: combine segment partials: img = sum_s (prod_{t<s} P_t) * C_s
// ---------------------------------------------------------------------------
__global__ void combine_kernel(float* __restrict__ out)
{
    int p = blockIdx.x * blockDim.x + threadIdx.x;
    if (p >= NPIX) return;
    float T = 1.0f, cr = 0.0f, cg = 0.0f, cb = 0.0f;
    #pragma unroll
    for (int s = 0; s < NSEG; s++) {
        float4 v = g_seg[s * NPIX + p];
        cr = fmaf(T, v.x, cr);
        cg = fmaf(T, v.y, cg);
        cb = fmaf(T, v.z, cb);
        T *= v.w;
    }
    out[p*3 + 0] = cr;
    out[p*3 + 1] = cg;
    out[p*3 + 2] = cb;
}

// ---------------------------------------------------------------------------
extern "C" void kernel_launch(void* const* d_in, const int* in_sizes, int n_in,
                              void* d_out, int out_size)
{
    const float* pos   = (const float*)d_in[0];
    const float* rgb   = (const float*)d_in[1];
    const float* opa   = (const float*)d_in[2];
    const float* quat  = (const float*)d_in[3];
    const float* scale = (const float*)d_in[4];
    const float* wq    = (const float*)d_in[5];
    const float* wt    = (const float*)d_in[6];
    float* out = (float*)d_out;

    prep_kernel<<<NG/256, 256>>>(pos, rgb, opa, quat, scale, wq, wt);
    sort_kernel<<<1, 1024>>>();
    render_kernel<<<dim3(64, NSEG), SEG_LEN>>>();
    combine_kernel<<<NPIX/256, 256>>>(out);
}

// round 13
// speedup vs baseline: 1.7887x; 1.7774x over previous
#include <cuda_runtime.h>
#include <math.h>

// Problem constants
#define NG    2048
#define HH    128
#define WW    128
#define NPIX  (HH*WW)

// ---------------- scratch (__device__ globals; no allocation allowed) -------
__device__ float  g_attr[NG][12];  // u,v,hA,B,hC,opa_m,r,g,b,key,ru,rv
__device__ int    g_rank[NG];
__device__ int    g_rank_done;
__device__ int    g_scatter_done;
__device__ float4 g_rec0[NG];      // u, v, -0.5A, -0.5C   (sorted)
__device__ float  g_recB[NG];      // B                    (sorted)
__device__ float4 g_rec1[NG];      // opa_m, r, g, b       (sorted)
__device__ float4 g_cull[NG];      // u, v, ru, rv         (sorted; ru<0 => masked)

// ---------------------------------------------------------------------------
// Kernel 1: per-gaussian preprocessing + counter/rank reset
// ---------------------------------------------------------------------------
__global__ void prep_kernel(const float* __restrict__ pos,
                            const float* __restrict__ rgb,
                            const float* __restrict__ opa,
                            const float* __restrict__ quat,
                            const float* __restrict__ scale,
                            const float* __restrict__ wq,
                            const float* __restrict__ wt)
{
    int n = blockIdx.x * blockDim.x + threadIdx.x;
    if (n >= NG) return;
    g_rank[n] = 0;
    if (n == 0) { g_rank_done = 0; g_scatter_done = 0; }

    // world->camera rotation from quaternion (normalized with +1e-12)
    float qw = wq[0], qx = wq[1], qy = wq[2], qz = wq[3];
    float qn = sqrtf(qw*qw + qx*qx + qy*qy + qz*qz) + 1e-12f;
    qw /= qn; qx /= qn; qy /= qn; qz /= qn;
    float r00 = 1.f - 2.f*(qy*qy + qz*qz), r01 = 2.f*(qx*qy - qw*qz), r02 = 2.f*(qx*qz + qw*qy);
    float r10 = 2.f*(qx*qy + qw*qz), r11 = 1.f - 2.f*(qx*qx + qz*qz), r12 = 2.f*(qy*qz - qw*qx);
    float r20 = 2.f*(qx*qz - qw*qy), r21 = 2.f*(qy*qz + qw*qx), r22 = 1.f - 2.f*(qx*qx + qy*qy);

    float p0 = pos[n*3+0], p1 = pos[n*3+1], p2 = pos[n*3+2];
    float x = r00*p0 + r01*p1 + r02*p2 + wt[0];
    float y = r10*p0 + r11*p1 + r12*p2 + wt[1];
    float z = r20*p0 + r21*p1 + r22*p2 + wt[2];

    float dnorm = sqrtf(x*x + y*y + z*z);
    bool  mask  = z > 1.1f;
    float zs    = mask ? z : 1.0f;
    float u     = x / zs;
    float v     = y / zs;
    mask = mask && (fabsf(u) < 0.64f) && (fabsf(v) < 0.64f);

    float iz   = 1.0f / zs;
    float iz2  = iz * iz;

    // rows 0,1 of JW = J @ rot
    float xz2 = x * iz2, yz2 = y * iz2;
    float jw00 = iz*r00 - xz2*r20, jw01 = iz*r01 - xz2*r21, jw02 = iz*r02 - xz2*r22;
    float jw10 = iz*r10 - yz2*r20, jw11 = iz*r11 - yz2*r21, jw12 = iz*r12 - yz2*r22;

    // gaussian rotation
    float gw = quat[n*4+0], gx = quat[n*4+1], gy = quat[n*4+2], gz = quat[n*4+3];
    float gn = sqrtf(gw*gw + gx*gx + gy*gy + gz*gz) + 1e-12f;
    gw /= gn; gx /= gn; gy /= gn; gz /= gn;
    float g00 = 1.f - 2.f*(gy*gy + gz*gz), g01 = 2.f*(gx*gy - gw*gz), g02 = 2.f*(gx*gz + gw*gy);
    float g10 = 2.f*(gx*gy + gw*gz), g11 = 1.f - 2.f*(gx*gx + gz*gz), g12 = 2.f*(gy*gz - gw*gx);
    float g20 = 2.f*(gx*gz - gw*gy), g21 = 2.f*(gy*gz + gw*gx), g22 = 1.f - 2.f*(gx*gx + gy*gy);

    float sx = scale[n*3+0], sy = scale[n*3+1], sz = scale[n*3+2];
    float a00 = g00*sx, a01 = g01*sy, a02 = g02*sz;
    float a10 = g10*sx, a11 = g11*sy, a12 = g12*sz;
    float a20 = g20*sx, a21 = g21*sy, a22 = g22*sz;

    // cov3d = RS RS^T (symmetric)
    float c00 = a00*a00 + a01*a01 + a02*a02;
    float c01 = a00*a10 + a01*a11 + a02*a12;
    float c02 = a00*a20 + a01*a21 + a02*a22;
    float c11 = a10*a10 + a11*a11 + a12*a12;
    float c12 = a10*a20 + a11*a21 + a12*a22;
    float c22 = a20*a20 + a21*a21 + a22*a22;

    float t00 = c00*jw00 + c01*jw01 + c02*jw02;
    float t01 = c01*jw00 + c11*jw01 + c12*jw02;
    float t02 = c02*jw00 + c12*jw01 + c22*jw02;
    float t10 = c00*jw10 + c01*jw11 + c02*jw12;
    float t11 = c01*jw10 + c11*jw11 + c12*jw12;
    float t12 = c02*jw10 + c12*jw11 + c22*jw12;

    float a = jw00*t00 + jw01*t01 + jw02*t02 + 1e-6f;
    float b = jw00*t10 + jw01*t11 + jw02*t12;
    float c = jw10*t10 + jw11*t11 + jw12*t12 + 1e-6f;

    float inv_det = 1.0f / fmaxf(a*c - b*b, 1e-12f);
    float A = c * inv_det;
    float B = b * inv_det;
    float C = a * inv_det;

    g_attr[n][0] = u;
    g_attr[n][1] = v;
    g_attr[n][2] = -0.5f * A;
    g_attr[n][3] = B;
    g_attr[n][4] = -0.5f * C;
    g_attr[n][5] = mask ? opa[n] : 0.0f;
    g_attr[n][6] = rgb[n*3+0];
    g_attr[n][7] = rgb[n*3+1];
    g_attr[n][8] = rgb[n*3+2];
    g_attr[n][9] = mask ? dnorm : INFINITY;
    // bbox half-extents of the power=-18 ellipse: |dx|max = sqrt(36*cov_xx)
    g_attr[n][10] = mask ? 6.0f * sqrtf(a) : -1.0f;
    g_attr[n][11] = 6.0f * sqrtf(c);
}

// ---------------------------------------------------------------------------
// Kernel 2 (mega): blocks 0..63   = rank partials (8 gaussian-groups x 8 key-chunks)
//                  blocks 0,9,..63 (bg==bc, 8 of them) = scatter by rank after spin
//                  blocks 64..127 = per-tile culled render after spin
// All 128 blocks are simultaneously resident (128 < 148 SMs) => spin-safe.
// ---------------------------------------------------------------------------
__global__ void __launch_bounds__(256) mega_kernel(float* __restrict__ out)
{
    int b   = blockIdx.x;
    int tid = threadIdx.x;

    if (b < 64) {
        // ---------------- rank partial ----------------
        int bg = b & 7;        // gaussian group
        int bc = b >> 3;       // key chunk
        __shared__ float s_k[256];
        s_k[tid] = g_attr[bc*256 + tid][9];
        __syncthreads();

        int   gi    = bg*256 + tid;
        float ki    = g_attr[gi][9];
        int   jbase = bc*256;
        int   r     = 0;
        #pragma unroll 8
        for (int j = 0; j < 256; j++) {
            float kj = s_k[j];
            r += (kj < ki) || (kj == ki && (jbase + j) < gi);
        }
        atomicAdd(&g_rank[gi], r);
        __threadfence();
        __syncthreads();
        if (tid == 0) atomicAdd(&g_rank_done, 1);

        if (bg == bc) {
            // ---------------- scatter (8 blocks) ----------------
            if (tid == 0) { while (*((volatile int*)&g_rank_done) < 64) { } }
            __syncthreads();
            int g2 = bg*256 + tid;
            int rr = *((volatile int*)&g_rank[g2]);
            float u = g_attr[g2][0], v = g_attr[g2][1];
            g_rec0[rr] = make_float4(u, v, g_attr[g2][2], g_attr[g2][4]);
            g_recB[rr] = g_attr[g2][3];
            g_rec1[rr] = make_float4(g_attr[g2][5], g_attr[g2][6], g_attr[g2][7], g_attr[g2][8]);
            g_cull[rr] = make_float4(u, v, g_attr[g2][10], g_attr[g2][11]);
            __threadfence();
            __syncthreads();
            if (tid == 0) atomicAdd(&g_scatter_done, 1);
        }
        return;
    }

    // ---------------- render (64 tile blocks) ----------------
    if (tid == 0) { while (*((volatile int*)&g_scatter_done) < 8) { } }
    __syncthreads();

    int tile = b - 64;
    int tx = tile & 7, ty = tile >> 3;
    float ulo = (tx*16 +  0.5f - 64.f) * 0.01f;
    float uhi = (tx*16 + 15.5f - 64.f) * 0.01f;
    float vlo = (ty*16 +  0.5f - 64.f) * 0.01f;
    float vhi = (ty*16 + 15.5f - 64.f) * 0.01f;

    __shared__ unsigned short s_list[NG];
    __shared__ int s_wcnt[8], s_woff[8];
    __shared__ int s_base;
    if (tid == 0) s_base = 0;
    int lane = tid & 31, wid = tid >> 5;
    __syncthreads();

    // order-preserving compaction of tile-overlapping gaussians (sorted order)
    for (int c = 0; c < 8; c++) {
        int g = c*256 + tid;
        float4 cu = g_cull[g];   // u,v,ru,rv  (ru<0 => masked)
        bool pred = (cu.z >= 0.f)
                 && (cu.x - cu.z <= uhi) && (cu.x + cu.z >= ulo)
                 && (cu.y - cu.w <= vhi) && (cu.y + cu.w >= vlo);
        unsigned m = __ballot_sync(0xffffffffu, pred);
        if (lane == 0) s_wcnt[wid] = __popc(m);
        __syncthreads();
        if (tid == 0) {
            int acc = s_base;
            #pragma unroll
            for (int w = 0; w < 8; w++) { s_woff[w] = acc; acc += s_wcnt[w]; }
            s_base = acc;
        }
        __syncthreads();
        if (pred)
            s_list[s_woff[wid] + __popc(m & ((1u << lane) - 1u))] = (unsigned short)g;
    }
    __syncthreads();
    int cnt = s_base;

    __shared__ float4 t0[256];
    __shared__ float  tB[256];
    __shared__ float4 t1[256];

    int px = tx*16 + (tid & 15);
    int py = ty*16 + (tid >> 4);
    float pu = (px + 0.5f - 64.f) * 0.01f;
    float pv = (py + 0.5f - 64.f) * 0.01f;

    float T = 1.f, cr = 0.f, cg = 0.f, cb = 0.f;

    for (int start = 0; start < cnt; start += 256) {
        int mlen = min(256, cnt - start);
        __syncthreads();
        if (tid < mlen) {
            int idx = s_list[start + tid];
            t0[tid] = g_rec0[idx];
            tB[tid] = g_recB[idx];
            t1[tid] = g_rec1[idx];
        }
        __syncthreads();
        for (int i = 0; i < mlen; i++) {
            float4 a = t0[i];
            float dx = pu - a.x;
            float dy = pv - a.y;
            float power = a.z*dx*dx + a.w*dy*dy + tB[i]*dx*dy;
            // exp(-18)~1.5e-8; T<1e-5 lanes contribute <1e-5 abs
            if (__any_sync(0xffffffffu, power > -18.0f && T > 1e-5f)) {
                float4 q = t1[i];
                float al = fminf(q.x * __expf(fminf(power, 0.f)), 0.99f);
                float w  = T * al;
                cr = fmaf(w, q.y, cr);
                cg = fmaf(w, q.z, cg);
                cb = fmaf(w, q.w, cb);
                T -= w;
            }
        }
        if (__syncthreads_and(T < 1e-5f)) break;
    }

    int p = py * WW + px;
    out[p*3 + 0] = cr;
    out[p*3 + 1] = cg;
    out[p*3 + 2] = cb;
}

// ---------------------------------------------------------------------------
extern "C" void kernel_launch(void* const* d_in, const int* in_sizes, int n_in,
                              void* d_out, int out_size)
{
    const float* pos   = (const float*)d_in[0];
    const float* rgb   = (const float*)d_in[1];
    const float* opa   = (const float*)d_in[2];
    const float* quat  = (const float*)d_in[3];
    const float* scale = (const float*)d_in[4];
    const float* wq    = (const float*)d_in[5];
    const float* wt    = (const float*)d_in[6];
    float* out = (float*)d_out;

    prep_kernel<<<NG/256, 256>>>(pos, rgb, opa, quat, scale, wq, wt);
    mega_kernel<<<128, 256>>>(out);
}

// round 14
// speedup vs baseline: 2.0639x; 1.1538x over previous
#include <cuda_runtime.h>
#include <cuda_fp16.h>
#include <math.h>

// Problem constants
#define NG    2048
#define HH    128
#define WW    128

// 128 tiles of 16x8 px, 128 blocks x 128 threads (all co-resident on 148 SMs)
#define NBLK  128
#define NTHR  128

// ---------------- scratch (__device__ globals; no allocation allowed) -------
__device__ float4 g_rec0[NG];   // u, v, -0.5A, -0.5C
__device__ float  g_recB[NG];   // B
__device__ float4 g_rec1[NG];   // opa_m, r, g, b
__device__ float4 g_cull[NG];   // u, v, depth, half2(ru,rv)  (ru<0 => masked)
__device__ int    g_prep_done;
__device__ int    g_fin_done;

// ---------------------------------------------------------------------------
__global__ void __launch_bounds__(NTHR) splat_kernel(
    const float* __restrict__ pos,
    const float* __restrict__ rgb,
    const float* __restrict__ opa,
    const float* __restrict__ quat,
    const float* __restrict__ scale,
    const float* __restrict__ wq,
    const float* __restrict__ wt,
    float* __restrict__ out)
{
    int b   = blockIdx.x;
    int tid = threadIdx.x;

    // ================= phase 1: prep (16 gaussians per block) ==============
    if (tid < 16) {
        int n = b * 16 + tid;

        float qw = wq[0], qx = wq[1], qy = wq[2], qz = wq[3];
        float qn = sqrtf(qw*qw + qx*qx + qy*qy + qz*qz) + 1e-12f;
        qw /= qn; qx /= qn; qy /= qn; qz /= qn;
        float r00 = 1.f - 2.f*(qy*qy + qz*qz), r01 = 2.f*(qx*qy - qw*qz), r02 = 2.f*(qx*qz + qw*qy);
        float r10 = 2.f*(qx*qy + qw*qz), r11 = 1.f - 2.f*(qx*qx + qz*qz), r12 = 2.f*(qy*qz - qw*qx);
        float r20 = 2.f*(qx*qz - qw*qy), r21 = 2.f*(qy*qz + qw*qx), r22 = 1.f - 2.f*(qx*qx + qy*qy);

        float p0 = pos[n*3+0], p1 = pos[n*3+1], p2 = pos[n*3+2];
        float x = r00*p0 + r01*p1 + r02*p2 + wt[0];
        float y = r10*p0 + r11*p1 + r12*p2 + wt[1];
        float z = r20*p0 + r21*p1 + r22*p2 + wt[2];

        float dnorm = sqrtf(x*x + y*y + z*z);
        bool  mask  = z > 1.1f;
        float zs    = mask ? z : 1.0f;
        float u     = x / zs;
        float v     = y / zs;
        mask = mask && (fabsf(u) < 0.64f) && (fabsf(v) < 0.64f);

        float iz  = 1.0f / zs;
        float iz2 = iz * iz;
        float xz2 = x * iz2, yz2 = y * iz2;
        float jw00 = iz*r00 - xz2*r20, jw01 = iz*r01 - xz2*r21, jw02 = iz*r02 - xz2*r22;
        float jw10 = iz*r10 - yz2*r20, jw11 = iz*r11 - yz2*r21, jw12 = iz*r12 - yz2*r22;

        float gw = quat[n*4+0], gx = quat[n*4+1], gy = quat[n*4+2], gz = quat[n*4+3];
        float gn = sqrtf(gw*gw + gx*gx + gy*gy + gz*gz) + 1e-12f;
        gw /= gn; gx /= gn; gy /= gn; gz /= gn;
        float g00 = 1.f - 2.f*(gy*gy + gz*gz), g01 = 2.f*(gx*gy - gw*gz), g02 = 2.f*(gx*gz + gw*gy);
        float g10 = 2.f*(gx*gy + gw*gz), g11 = 1.f - 2.f*(gx*gx + gz*gz), g12 = 2.f*(gy*gz - gw*gx);
        float g20 = 2.f*(gx*gz - gw*gy), g21 = 2.f*(gy*gz + gw*gx), g22 = 1.f - 2.f*(gx*gx + gy*gy);

        float sx = scale[n*3+0], sy = scale[n*3+1], sz = scale[n*3+2];
        float a00 = g00*sx, a01 = g01*sy, a02 = g02*sz;
        float a10 = g10*sx, a11 = g11*sy, a12 = g12*sz;
        float a20 = g20*sx, a21 = g21*sy, a22 = g22*sz;

        float c00 = a00*a00 + a01*a01 + a02*a02;
        float c01 = a00*a10 + a01*a11 + a02*a12;
        float c02 = a00*a20 + a01*a21 + a02*a22;
        float c11 = a10*a10 + a11*a11 + a12*a12;
        float c12 = a10*a20 + a11*a21 + a12*a22;
        float c22 = a20*a20 + a21*a21 + a22*a22;

        float t00 = c00*jw00 + c01*jw01 + c02*jw02;
        float t01 = c01*jw00 + c11*jw01 + c12*jw02;
        float t02 = c02*jw00 + c12*jw01 + c22*jw02;
        float t10 = c00*jw10 + c01*jw11 + c02*jw12;
        float t11 = c01*jw10 + c11*jw11 + c12*jw12;
        float t12 = c02*jw10 + c12*jw11 + c22*jw12;

        float a = jw00*t00 + jw01*t01 + jw02*t02 + 1e-6f;
        float bb= jw00*t10 + jw01*t11 + jw02*t12;
        float c = jw10*t10 + jw11*t11 + jw12*t12 + 1e-6f;

        float inv_det = 1.0f / fmaxf(a*c - bb*bb, 1e-12f);
        float A = c * inv_det;
        float B = bb * inv_det;
        float C = a * inv_det;

        g_rec0[n] = make_float4(u, v, -0.5f*A, -0.5f*C);
        g_recB[n] = B;
        g_rec1[n] = make_float4(mask ? opa[n] : 0.0f, rgb[n*3+0], rgb[n*3+1], rgb[n*3+2]);

        // power=-18 level-set bbox half-extents; round UP in half for safety
        __half ruh = mask ? __float2half_ru(6.0f * sqrtf(a)) : __float2half(-1.0f);
        __half rvh = __float2half_ru(6.0f * sqrtf(c));
        __half2 rr = __halves2half2(ruh, rvh);
        g_cull[n] = make_float4(u, v, mask ? dnorm : INFINITY,
                                __uint_as_float(*(unsigned*)&rr));
    }
    __syncthreads();
    __threadfence();
    if (tid == 0) atomicAdd(&g_prep_done, 1);

    // ================= spin until all prep complete =========================
    if (tid == 0) { while (*((volatile int*)&g_prep_done) < NBLK) { } }
    __syncthreads();
    __threadfence();

    // ================= phase 2: per-tile cull (unsorted append) ============
    int tx = b & 7, ty = b >> 3;          // tile = 16x8 px
    float ulo = (tx*16 +  0.5f - 64.f) * 0.01f;
    float uhi = (tx*16 + 15.5f - 64.f) * 0.01f;
    float vlo = (ty*8  +  0.5f - 64.f) * 0.01f;
    float vhi = (ty*8  +  7.5f - 64.f) * 0.01f;

    __shared__ unsigned long long s_keys[NG];
    __shared__ int s_cnt;
    if (tid == 0) s_cnt = 0;
    __syncthreads();

    #pragma unroll 4
    for (int c = 0; c < NG / NTHR; c++) {
        int g = c * NTHR + tid;
        float4 cu = g_cull[g];
        unsigned hb = __float_as_uint(cu.w);
        float2 rad = __half22float2(*(__half2*)&hb);
        if (rad.x >= 0.f &&
            cu.x - rad.x <= uhi && cu.x + rad.x >= ulo &&
            cu.y - rad.y <= vhi && cu.y + rad.y >= vlo) {
            int p = atomicAdd(&s_cnt, 1);
            s_keys[p] = (((unsigned long long)__float_as_uint(cu.z)) << 32)
                      | (unsigned)g;
        }
    }
    __syncthreads();
    int cnt = s_cnt;

    // ================= phase 3: local bitonic sort by (depth, idx) =========
    int n2 = 1;
    while (n2 < cnt) n2 <<= 1;
    for (int e = cnt + tid; e < n2; e += NTHR) s_keys[e] = ~0ull;

    for (int k = 2; k <= n2; k <<= 1) {
        for (int j = k >> 1; j > 0; j >>= 1) {
            __syncthreads();
            for (int e = tid; e < n2; e += NTHR) {
                int ixj = e ^ j;
                if (ixj > e) {
                    unsigned long long ka = s_keys[e], kb = s_keys[ixj];
                    bool up = ((e & k) == 0);
                    if ((ka > kb) == up) { s_keys[e] = kb; s_keys[ixj] = ka; }
                }
            }
        }
    }
    __syncthreads();

    // ================= phase 4: front-to-back blend ========================
    __shared__ float4 t0[NTHR];
    __shared__ float  tB[NTHR];
    __shared__ float4 t1[NTHR];

    int px = tx*16 + (tid & 15);
    int py = ty*8  + (tid >> 4);
    float pu = (px + 0.5f - 64.f) * 0.01f;
    float pv = (py + 0.5f - 64.f) * 0.01f;

    float T = 1.f, cr = 0.f, cg = 0.f, cb = 0.f;

    for (int start = 0; start < cnt; start += NTHR) {
        int mlen = min(NTHR, cnt - start);
        __syncthreads();
        if (tid < mlen) {
            int idx = (int)(s_keys[start + tid] & 0xffffffffu);
            t0[tid] = g_rec0[idx];
            tB[tid] = g_recB[idx];
            t1[tid] = g_rec1[idx];
        }
        __syncthreads();
        for (int i = 0; i < mlen; i++) {
            float4 a = t0[i];
            float dx = pu - a.x;
            float dy = pv - a.y;
            float power = a.z*dx*dx + a.w*dy*dy + tB[i]*dx*dy;
            // exp(-18)~1.5e-8 and saturated lanes (T<1e-5) contribute <1e-5 abs
            if (__any_sync(0xffffffffu, power > -18.0f && T > 1e-5f)) {
                float4 q = t1[i];
                float al = fminf(q.x * __expf(fminf(power, 0.f)), 0.99f);
                float w  = T * al;
                cr = fmaf(w, q.y, cr);
                cg = fmaf(w, q.z, cg);
                cb = fmaf(w, q.w, cb);
                T -= w;
            }
        }
        if (__syncthreads_and(T < 1e-5f)) break;
    }

    int p = py * WW + px;
    out[p*3 + 0] = cr;
    out[p*3 + 1] = cg;
    out[p*3 + 2] = cb;

    // ================= counter self-reset for next graph replay ============
    __syncthreads();
    if (tid == 0) {
        int o = atomicAdd(&g_fin_done, 1);
        if (o == NBLK - 1) {
            g_prep_done = 0;
            g_fin_done  = 0;
            __threadfence();
        }
    }
}

// ---------------------------------------------------------------------------
extern "C" void kernel_launch(void* const* d_in, const int* in_sizes, int n_in,
                              void* d_out, int out_size)
{
    const float* pos   = (const float*)d_in[0];
    const float* rgb   = (const float*)d_in[1];
    const float* opa   = (const float*)d_in[2];
    const float* quat  = (const float*)d_in[3];
    const float* scale = (const float*)d_in[4];
    const float* wq    = (const float*)d_in[5];
    const float* wt    = (const float*)d_in[6];
    float* out = (float*)d_out;

    splat_kernel<<<NBLK, NTHR>>>(pos, rgb, opa, quat, scale, wq, wt, out);
}

// round 15
// speedup vs baseline: 2.6265x; 1.2726x over previous
#include <cuda_runtime.h>
#include <cuda_fp16.h>
#include <math.h>

// Problem constants
#define NG    2048
#define HH    128
#define WW    128

// 128 tiles of 16x8 px; 128 blocks x 256 threads (2 depth segments per tile)
#define NBLK  128
#define NTHR  256
#define HALFT 128

// ---------------- scratch (__device__ globals; no allocation allowed) -------
__device__ float4 g_rec0[NG];   // u, v, -0.5A, -0.5C
__device__ float  g_recB[NG];   // B
__device__ float4 g_rec1[NG];   // opa_m, r, g, b
__device__ float4 g_cull[NG];   // u, v, depth, half2(ru,rv)  (ru<0 => masked)
__device__ int    g_prep_done;
__device__ int    g_fin_done;

// ---------------------------------------------------------------------------
__global__ void __launch_bounds__(NTHR) splat_kernel(
    const float* __restrict__ pos,
    const float* __restrict__ rgb,
    const float* __restrict__ opa,
    const float* __restrict__ quat,
    const float* __restrict__ scale,
    const float* __restrict__ wq,
    const float* __restrict__ wt,
    float* __restrict__ out)
{
    int b   = blockIdx.x;
    int tid = threadIdx.x;

    // ================= phase 1: prep (16 gaussians per block) ==============
    if (tid < 16) {
        int n = b * 16 + tid;

        float qw = wq[0], qx = wq[1], qy = wq[2], qz = wq[3];
        float qn = sqrtf(qw*qw + qx*qx + qy*qy + qz*qz) + 1e-12f;
        qw /= qn; qx /= qn; qy /= qn; qz /= qn;
        float r00 = 1.f - 2.f*(qy*qy + qz*qz), r01 = 2.f*(qx*qy - qw*qz), r02 = 2.f*(qx*qz + qw*qy);
        float r10 = 2.f*(qx*qy + qw*qz), r11 = 1.f - 2.f*(qx*qx + qz*qz), r12 = 2.f*(qy*qz - qw*qx);
        float r20 = 2.f*(qx*qz - qw*qy), r21 = 2.f*(qy*qz + qw*qx), r22 = 1.f - 2.f*(qx*qx + qy*qy);

        float p0 = pos[n*3+0], p1 = pos[n*3+1], p2 = pos[n*3+2];
        float x = r00*p0 + r01*p1 + r02*p2 + wt[0];
        float y = r10*p0 + r11*p1 + r12*p2 + wt[1];
        float z = r20*p0 + r21*p1 + r22*p2 + wt[2];

        float dnorm = sqrtf(x*x + y*y + z*z);
        bool  mask  = z > 1.1f;
        float zs    = mask ? z : 1.0f;
        float u     = x / zs;
        float v     = y / zs;
        mask = mask && (fabsf(u) < 0.64f) && (fabsf(v) < 0.64f);

        float iz  = 1.0f / zs;
        float iz2 = iz * iz;
        float xz2 = x * iz2, yz2 = y * iz2;
        float jw00 = iz*r00 - xz2*r20, jw01 = iz*r01 - xz2*r21, jw02 = iz*r02 - xz2*r22;
        float jw10 = iz*r10 - yz2*r20, jw11 = iz*r11 - yz2*r21, jw12 = iz*r12 - yz2*r22;

        float gw = quat[n*4+0], gx = quat[n*4+1], gy = quat[n*4+2], gz = quat[n*4+3];
        float gn = sqrtf(gw*gw + gx*gx + gy*gy + gz*gz) + 1e-12f;
        gw /= gn; gx /= gn; gy /= gn; gz /= gn;
        float g00 = 1.f - 2.f*(gy*gy + gz*gz), g01 = 2.f*(gx*gy - gw*gz), g02 = 2.f*(gx*gz + gw*gy);
        float g10 = 2.f*(gx*gy + gw*gz), g11 = 1.f - 2.f*(gx*gx + gz*gz), g12 = 2.f*(gy*gz - gw*gx);
        float g20 = 2.f*(gx*gz - gw*gy), g21 = 2.f*(gy*gz + gw*gx), g22 = 1.f - 2.f*(gx*gx + gy*gy);

        float sx = scale[n*3+0], sy = scale[n*3+1], sz = scale[n*3+2];
        float a00 = g00*sx, a01 = g01*sy, a02 = g02*sz;
        float a10 = g10*sx, a11 = g11*sy, a12 = g12*sz;
        float a20 = g20*sx, a21 = g21*sy, a22 = g22*sz;

        float c00 = a00*a00 + a01*a01 + a02*a02;
        float c01 = a00*a10 + a01*a11 + a02*a12;
        float c02 = a00*a20 + a01*a21 + a02*a22;
        float c11 = a10*a10 + a11*a11 + a12*a12;
        float c12 = a10*a20 + a11*a21 + a12*a22;
        float c22 = a20*a20 + a21*a21 + a22*a22;

        float t00 = c00*jw00 + c01*jw01 + c02*jw02;
        float t01 = c01*jw00 + c11*jw01 + c12*jw02;
        float t02 = c02*jw00 + c12*jw01 + c22*jw02;
        float t10 = c00*jw10 + c01*jw11 + c02*jw12;
        float t11 = c01*jw10 + c11*jw11 + c12*jw12;
        float t12 = c02*jw10 + c12*jw11 + c22*jw12;

        float a = jw00*t00 + jw01*t01 + jw02*t02 + 1e-6f;
        float bb= jw00*t10 + jw01*t11 + jw02*t12;
        float c = jw10*t10 + jw11*t11 + jw12*t12 + 1e-6f;

        float inv_det = 1.0f / fmaxf(a*c - bb*bb, 1e-12f);
        float A = c * inv_det;
        float B = bb * inv_det;
        float C = a * inv_det;

        g_rec0[n] = make_float4(u, v, -0.5f*A, -0.5f*C);
        g_recB[n] = B;
        g_rec1[n] = make_float4(mask ? opa[n] : 0.0f, rgb[n*3+0], rgb[n*3+1], rgb[n*3+2]);

        __half ruh = mask ? __float2half_ru(6.0f * sqrtf(a)) : __float2half(-1.0f);
        __half rvh = __float2half_ru(6.0f * sqrtf(c));
        __half2 rr = __halves2half2(ruh, rvh);
        g_cull[n] = make_float4(u, v, mask ? dnorm : INFINITY,
                                __uint_as_float(*(unsigned*)&rr));
    }
    __syncthreads();
    __threadfence();
    if (tid == 0) atomicAdd(&g_prep_done, 1);

    // ================= spin until all prep complete =========================
    if (tid == 0) { while (*((volatile int*)&g_prep_done) < NBLK) { } }
    __syncthreads();
    __threadfence();

    // ================= phase 2: per-tile cull (unsorted append) ============
    int tx = b & 7, ty = b >> 3;          // tile = 16x8 px
    float ulo = (tx*16 +  0.5f - 64.f) * 0.01f;
    float uhi = (tx*16 + 15.5f - 64.f) * 0.01f;
    float vlo = (ty*8  +  0.5f - 64.f) * 0.01f;
    float vhi = (ty*8  +  7.5f - 64.f) * 0.01f;

    __shared__ unsigned long long s_keys[NG];
    __shared__ int s_cnt;
    if (tid == 0) s_cnt = 0;
    __syncthreads();

    #pragma unroll 4
    for (int c = 0; c < NG / NTHR; c++) {
        int g = c * NTHR + tid;
        float4 cu = g_cull[g];
        unsigned hb = __float_as_uint(cu.w);
        float2 rad = __half22float2(*(__half2*)&hb);
        if (rad.x >= 0.f &&
            cu.x - rad.x <= uhi && cu.x + rad.x >= ulo &&
            cu.y - rad.y <= vhi && cu.y + rad.y >= vlo) {
            int p = atomicAdd(&s_cnt, 1);
            s_keys[p] = (((unsigned long long)__float_as_uint(cu.z)) << 32)
                      | (unsigned)g;
        }
    }
    __syncthreads();
    int cnt = s_cnt;

    // ================= phase 3: local bitonic sort by (depth, idx) =========
    int n2 = 1;
    while (n2 < cnt) n2 <<= 1;
    for (int e = cnt + tid; e < n2; e += NTHR) s_keys[e] = ~0ull;

    for (int k = 2; k <= n2; k <<= 1) {
        for (int j = k >> 1; j > 0; j >>= 1) {
            __syncthreads();
            for (int e = tid; e < n2; e += NTHR) {
                int ixj = e ^ j;
                if (ixj > e) {
                    unsigned long long ka = s_keys[e], kb = s_keys[ixj];
                    bool up = ((e & k) == 0);
                    if ((ka > kb) == up) { s_keys[e] = kb; s_keys[ixj] = ka; }
                }
            }
        }
    }
    __syncthreads();

    // ================= phase 4: two-segment front-to-back blend ============
    // threads [0,128)  : pixels, front half of sorted list
    // threads [128,256): SAME pixels, back half; combined exactly at the end
    __shared__ float4 t0[NTHR];
    __shared__ float  tB[NTHR];
    __shared__ float4 t1[NTHR];
    __shared__ float4 s_part[HALFT];

    int seg  = tid >> 7;          // 0 or 1
    int lt   = tid & (HALFT-1);   // pixel id within tile
    int half0 = (cnt + 1) >> 1;
    int half1 = cnt - half0;
    int segbase = seg ? half0 : 0;
    int seglen  = seg ? half1 : half0;

    int px = tx*16 + (lt & 15);
    int py = ty*8  + (lt >> 4);
    float pu = (px + 0.5f - 64.f) * 0.01f;
    float pv = (py + 0.5f - 64.f) * 0.01f;

    float T = 1.f, cr = 0.f, cg = 0.f, cb = 0.f;

    int rounds = (half0 + HALFT - 1) / HALFT;   // half0 >= half1
    for (int r = 0; r < rounds; r++) {
        int off  = r * HALFT;
        __syncthreads();
        if (off + lt < seglen) {
            int idx = (int)(s_keys[segbase + off + lt] & 0xffffffffu);
            t0[tid] = g_rec0[idx];
            tB[tid] = g_recB[idx];
            t1[tid] = g_rec1[idx];
        }
        __syncthreads();
        int mlen = min(HALFT, seglen - off);
        int sb   = seg * HALFT;
        for (int i = 0; i < mlen; i++) {
            float4 a = t0[sb + i];
            float dx = pu - a.x;
            float dy = pv - a.y;
            float power = a.z*dx*dx + a.w*dy*dy + tB[sb + i]*dx*dy;
            // exp(-18)~1.5e-8 and saturated lanes (T<1e-5) contribute <1e-5 abs
            if (__any_sync(0xffffffffu, power > -18.0f && T > 1e-5f)) {
                float4 q = t1[sb + i];
                float al = fminf(q.x * __expf(fminf(power, 0.f)), 0.99f);
                float w  = T * al;
                cr = fmaf(w, q.y, cr);
                cg = fmaf(w, q.z, cg);
                cb = fmaf(w, q.w, cb);
                T -= w;
            }
        }
        if (__syncthreads_and(T < 1e-5f)) break;
    }

    // exact combine: c = c0 + T0*c1 ; T = T0*T1
    __syncthreads();
    if (seg) s_part[lt] = make_float4(cr, cg, cb, T);
    __syncthreads();
    if (!seg) {
        float4 p1 = s_part[lt];
        cr = fmaf(T, p1.x, cr);
        cg = fmaf(T, p1.y, cg);
        cb = fmaf(T, p1.z, cb);
        int p = py * WW + px;
        out[p*3 + 0] = cr;
        out[p*3 + 1] = cg;
        out[p*3 + 2] = cb;
    }

    // ================= counter self-reset for next graph replay ============
    __syncthreads();
    if (tid == 0) {
        int o = atomicAdd(&g_fin_done, 1);
        if (o == NBLK - 1) {
            g_prep_done = 0;
            g_fin_done  = 0;
            __threadfence();
        }
    }
}

// ---------------------------------------------------------------------------
extern "C" void kernel_launch(void* const* d_in, const int* in_sizes, int n_in,
                              void* d_out, int out_size)
{
    const float* pos   = (const float*)d_in[0];
    const float* rgb   = (const float*)d_in[1];
    const float* opa   = (const float*)d_in[2];
    const float* quat  = (const float*)d_in[3];
    const float* scale = (const float*)d_in[4];
    const float* wq    = (const float*)d_in[5];
    const float* wt    = (const float*)d_in[6];
    float* out = (float*)d_out;

    splat_kernel<<<NBLK, NTHR>>>(pos, rgb, opa, quat, scale, wq, wt, out);
}

// round 16
// speedup vs baseline: 3.7505x; 1.4280x over previous
#include <cuda_runtime.h>
#include <cuda_fp16.h>
#include <math.h>

// Problem constants
#define NG    2048
#define HH    128
#define WW    128

// 128 tiles of 16x8 px; 128 blocks x 512 threads (4 depth segments per tile)
#define NBLK  128
#define NTHR  512
#define PIXT  128      // pixels per tile
#define NSEG  4

// ---------------- scratch (__device__ globals; no allocation allowed) -------
__device__ float4 g_rec0[NG];   // u, v, -0.5A, -0.5C
__device__ float  g_recB[NG];   // B
__device__ float4 g_rec1[NG];   // opa_m, r, g, b
__device__ float4 g_cull[NG];   // u, v, depth, half2(ru,rv)  (ru<0 => masked)
__device__ int    g_prep_done;
__device__ int    g_fin_done;

// ---------------------------------------------------------------------------
__global__ void __launch_bounds__(NTHR) splat_kernel(
    const float* __restrict__ pos,
    const float* __restrict__ rgb,
    const float* __restrict__ opa,
    const float* __restrict__ quat,
    const float* __restrict__ scale,
    const float* __restrict__ wq,
    const float* __restrict__ wt,
    float* __restrict__ out)
{
    int b   = blockIdx.x;
    int tid = threadIdx.x;

    // ================= phase 1: prep (16 gaussians per block) ==============
    if (tid < 16) {
        int n = b * 16 + tid;

        float qw = wq[0], qx = wq[1], qy = wq[2], qz = wq[3];
        float qn = sqrtf(qw*qw + qx*qx + qy*qy + qz*qz) + 1e-12f;
        qw /= qn; qx /= qn; qy /= qn; qz /= qn;
        float r00 = 1.f - 2.f*(qy*qy + qz*qz), r01 = 2.f*(qx*qy - qw*qz), r02 = 2.f*(qx*qz + qw*qy);
        float r10 = 2.f*(qx*qy + qw*qz), r11 = 1.f - 2.f*(qx*qx + qz*qz), r12 = 2.f*(qy*qz - qw*qx);
        float r20 = 2.f*(qx*qz - qw*qy), r21 = 2.f*(qy*qz + qw*qx), r22 = 1.f - 2.f*(qx*qx + qy*qy);

        float p0 = pos[n*3+0], p1 = pos[n*3+1], p2 = pos[n*3+2];
        float x = r00*p0 + r01*p1 + r02*p2 + wt[0];
        float y = r10*p0 + r11*p1 + r12*p2 + wt[1];
        float z = r20*p0 + r21*p1 + r22*p2 + wt[2];

        float dnorm = sqrtf(x*x + y*y + z*z);
        bool  mask  = z > 1.1f;
        float zs    = mask ? z : 1.0f;
        float u     = x / zs;
        float v     = y / zs;
        mask = mask && (fabsf(u) < 0.64f) && (fabsf(v) < 0.64f);

        float iz  = 1.0f / zs;
        float iz2 = iz * iz;
        float xz2 = x * iz2, yz2 = y * iz2;
        float jw00 = iz*r00 - xz2*r20, jw01 = iz*r01 - xz2*r21, jw02 = iz*r02 - xz2*r22;
        float jw10 = iz*r10 - yz2*r20, jw11 = iz*r11 - yz2*r21, jw12 = iz*r12 - yz2*r22;

        float gw = quat[n*4+0], gx = quat[n*4+1], gy = quat[n*4+2], gz = quat[n*4+3];
        float gn = sqrtf(gw*gw + gx*gx + gy*gy + gz*gz) + 1e-12f;
        gw /= gn; gx /= gn; gy /= gn; gz /= gn;
        float g00 = 1.f - 2.f*(gy*gy + gz*gz), g01 = 2.f*(gx*gy - gw*gz), g02 = 2.f*(gx*gz + gw*gy);
        float g10 = 2.f*(gx*gy + gw*gz), g11 = 1.f - 2.f*(gx*gx + gz*gz), g12 = 2.f*(gy*gz - gw*gx);
        float g20 = 2.f*(gx*gz - gw*gy), g21 = 2.f*(gy*gz + gw*gx), g22 = 1.f - 2.f*(gx*gx + gy*gy);

        float sx = scale[n*3+0], sy = scale[n*3+1], sz = scale[n*3+2];
        float a00 = g00*sx, a01 = g01*sy, a02 = g02*sz;
        float a10 = g10*sx, a11 = g11*sy, a12 = g12*sz;
        float a20 = g20*sx, a21 = g21*sy, a22 = g22*sz;

        float c00 = a00*a00 + a01*a01 + a02*a02;
        float c01 = a00*a10 + a01*a11 + a02*a12;
        float c02 = a00*a20 + a01*a21 + a02*a22;
        float c11 = a10*a10 + a11*a11 + a12*a12;
        float c12 = a10*a20 + a11*a21 + a12*a22;
        float c22 = a20*a20 + a21*a21 + a22*a22;

        float t00 = c00*jw00 + c01*jw01 + c02*jw02;
        float t01 = c01*jw00 + c11*jw01 + c12*jw02;
        float t02 = c02*jw00 + c12*jw01 + c22*jw02;
        float t10 = c00*jw10 + c01*jw11 + c02*jw12;
        float t11 = c01*jw10 + c11*jw11 + c12*jw12;
        float t12 = c02*jw10 + c12*jw11 + c22*jw12;

        float a = jw00*t00 + jw01*t01 + jw02*t02 + 1e-6f;
        float bb= jw00*t10 + jw01*t11 + jw02*t12;
        float c = jw10*t10 + jw11*t11 + jw12*t12 + 1e-6f;

        float inv_det = 1.0f / fmaxf(a*c - bb*bb, 1e-12f);
        float A = c * inv_det;
        float B = bb * inv_det;
        float C = a * inv_det;

        g_rec0[n] = make_float4(u, v, -0.5f*A, -0.5f*C);
        g_recB[n] = B;
        g_rec1[n] = make_float4(mask ? opa[n] : 0.0f, rgb[n*3+0], rgb[n*3+1], rgb[n*3+2]);

        __half ruh = mask ? __float2half_ru(6.0f * sqrtf(a)) : __float2half(-1.0f);
        __half rvh = __float2half_ru(6.0f * sqrtf(c));
        __half2 rr = __halves2half2(ruh, rvh);
        g_cull[n] = make_float4(u, v, mask ? dnorm : INFINITY,
                                __uint_as_float(*(unsigned*)&rr));
    }
    __syncthreads();
    __threadfence();
    if (tid == 0) atomicAdd(&g_prep_done, 1);

    // ================= spin until all prep complete =========================
    if (tid == 0) { while (*((volatile int*)&g_prep_done) < NBLK) { } }
    __syncthreads();
    __threadfence();

    // ================= phase 2: per-tile cull (unsorted append) ============
    int tx = b & 7, ty = b >> 3;          // tile = 16x8 px
    float ulo = (tx*16 +  0.5f - 64.f) * 0.01f;
    float uhi = (tx*16 + 15.5f - 64.f) * 0.01f;
    float vlo = (ty*8  +  0.5f - 64.f) * 0.01f;
    float vhi = (ty*8  +  7.5f - 64.f) * 0.01f;

    __shared__ unsigned long long s_keys[NG];
    __shared__ unsigned long long s_sorted[NG];
    __shared__ int s_cnt;
    if (tid == 0) s_cnt = 0;
    __syncthreads();

    #pragma unroll
    for (int c = 0; c < NG / NTHR; c++) {
        int g = c * NTHR + tid;
        float4 cu = g_cull[g];
        unsigned hb = __float_as_uint(cu.w);
        float2 rad = __half22float2(*(__half2*)&hb);
        if (rad.x >= 0.f &&
            cu.x - rad.x <= uhi && cu.x + rad.x >= ulo &&
            cu.y - rad.y <= vhi && cu.y + rad.y >= vlo) {
            int p = atomicAdd(&s_cnt, 1);
            s_keys[p] = (((unsigned long long)__float_as_uint(cu.z)) << 32)
                      | (unsigned)g;
        }
    }
    __syncthreads();
    int cnt = s_cnt;

    // ================= phase 3: rank sort (keys unique) ====================
    for (int e = tid; e < cnt; e += NTHR) {
        unsigned long long k = s_keys[e];
        int r = 0;
        for (int j = 0; j < cnt; j++) r += (s_keys[j] < k);
        s_sorted[r] = k;
    }
    __syncthreads();

    // ================= phase 4: four-segment front-to-back blend ===========
    __shared__ float4 t0[NTHR];
    __shared__ float  tB[NTHR];
    __shared__ float4 t1[NTHR];
    __shared__ float4 s_part[(NSEG-1) * PIXT];

    int seg = tid >> 7;             // 0..3
    int lt  = tid & (PIXT-1);       // pixel id within tile
    int segbase = (cnt * seg) >> 2;
    int segend  = (cnt * (seg+1)) >> 2;
    int seglen  = segend - segbase;

    int px = tx*16 + (lt & 15);
    int py = ty*8  + (lt >> 4);
    float pu = (px + 0.5f - 64.f) * 0.01f;
    float pv = (py + 0.5f - 64.f) * 0.01f;

    float T = 1.f, cr = 0.f, cg = 0.f, cb = 0.f;

    int rounds = (((cnt + 3) >> 2) + PIXT - 1) / PIXT;
    for (int r = 0; r < rounds; r++) {
        int off = r * PIXT;
        __syncthreads();
        if (off + lt < seglen) {
            int idx = (int)(s_sorted[segbase + off + lt] & 0xffffffffu);
            t0[tid] = g_rec0[idx];
            tB[tid] = g_recB[idx];
            t1[tid] = g_rec1[idx];
        }
        __syncthreads();
        int mlen = min(PIXT, seglen - off);
        int sb   = seg * PIXT;
        for (int i = 0; i < mlen; i++) {
            float4 a = t0[sb + i];
            float dx = pu - a.x;
            float dy = pv - a.y;
            float power = a.z*dx*dx + a.w*dy*dy + tB[sb + i]*dx*dy;
            // exp(-18)~1.5e-8 and saturated lanes (T<1e-5) contribute <1e-5 abs
            if (__any_sync(0xffffffffu, power > -18.0f && T > 1e-5f)) {
                float4 q = t1[sb + i];
                float al = fminf(q.x * __expf(fminf(power, 0.f)), 0.99f);
                float w  = T * al;
                cr = fmaf(w, q.y, cr);
                cg = fmaf(w, q.z, cg);
                cb = fmaf(w, q.w, cb);
                T -= w;
            }
        }
        if (__syncthreads_and(T < 1e-5f)) break;
    }

    // exact combine: c = c0 + T0*(c1 + T1*(c2 + T2*c3))
    __syncthreads();
    if (seg) s_part[(seg-1) * PIXT + lt] = make_float4(cr, cg, cb, T);
    __syncthreads();
    if (!seg) {
        float4 p1 = s_part[0*PIXT + lt];
        float4 p2 = s_part[1*PIXT + lt];
        float4 p3 = s_part[2*PIXT + lt];
        // fold back-to-front
        float ccr = fmaf(p2.w, p3.x, p2.x);
        float ccg = fmaf(p2.w, p3.y, p2.y);
        float ccb = fmaf(p2.w, p3.z, p2.z);
        ccr = fmaf(p1.w, ccr, p1.x);
        ccg = fmaf(p1.w, ccg, p1.y);
        ccb = fmaf(p1.w, ccb, p1.z);
        cr  = fmaf(T, ccr, cr);
        cg  = fmaf(T, ccg, cg);
        cb  = fmaf(T, ccb, cb);
        int p = py * WW + px;
        out[p*3 + 0] = cr;
        out[p*3 + 1] = cg;
        out[p*3 + 2] = cb;
    }

    // ================= counter self-reset for next graph replay ============
    __syncthreads();
    if (tid == 0) {
        int o = atomicAdd(&g_fin_done, 1);
        if (o == NBLK - 1) {
            g_prep_done = 0;
            g_fin_done  = 0;
            __threadfence();
        }
    }
}

// ---------------------------------------------------------------------------
extern "C" void kernel_launch(void* const* d_in, const int* in_sizes, int n_in,
                              void* d_out, int out_size)
{
    const float* pos   = (const float*)d_in[0];
    const float* rgb   = (const float*)d_in[1];
    const float* opa   = (const float*)d_in[2];
    const float* quat  = (const float*)d_in[3];
    const float* scale = (const float*)d_in[4];
    const float* wq    = (const float*)d_in[5];
    const float* wt    = (const float*)d_in[6];
    float* out = (float*)d_out;

    splat_kernel<<<NBLK, NTHR>>>(pos, rgb, opa, quat, scale, wq, wt, out);
}

// round 17
// speedup vs baseline: 3.7586x; 1.0022x over previous
#include <cuda_runtime.h>
#include <cuda_fp16.h>
#include <math.h>

// Problem constants
#define NG    2048
#define HH    128
#define WW    128

// 128 tiles of 16x8 px; 128 blocks x 1024 threads (8 depth segments per tile)
#define NBLK  128
#define NTHR  1024
#define PIXT  128      // pixels per tile
#define NSEG  8

// ---------------- scratch (__device__ globals; no allocation allowed) -------
__device__ float4 g_rec0[NG];   // u, v, -0.5A, -0.5C
__device__ float  g_recB[NG];   // B
__device__ float4 g_rec1[NG];   // opa_m, r, g, b
__device__ float4 g_cull[NG];   // u, v, depth, half2(ru,rv)  (ru<0 => masked)
__device__ int    g_prep_done;
__device__ int    g_fin_done;

// ---------------------------------------------------------------------------
__global__ void __launch_bounds__(NTHR) splat_kernel(
    const float* __restrict__ pos,
    const float* __restrict__ rgb,
    const float* __restrict__ opa,
    const float* __restrict__ quat,
    const float* __restrict__ scale,
    const float* __restrict__ wq,
    const float* __restrict__ wt,
    float* __restrict__ out)
{
    int b   = blockIdx.x;
    int tid = threadIdx.x;

    // ================= phase 1: prep (16 gaussians per block) ==============
    if (tid < 16) {
        int n = b * 16 + tid;

        float qw = wq[0], qx = wq[1], qy = wq[2], qz = wq[3];
        float qn = sqrtf(qw*qw + qx*qx + qy*qy + qz*qz) + 1e-12f;
        qw /= qn; qx /= qn; qy /= qn; qz /= qn;
        float r00 = 1.f - 2.f*(qy*qy + qz*qz), r01 = 2.f*(qx*qy - qw*qz), r02 = 2.f*(qx*qz + qw*qy);
        float r10 = 2.f*(qx*qy + qw*qz), r11 = 1.f - 2.f*(qx*qx + qz*qz), r12 = 2.f*(qy*qz - qw*qx);
        float r20 = 2.f*(qx*qz - qw*qy), r21 = 2.f*(qy*qz + qw*qx), r22 = 1.f - 2.f*(qx*qx + qy*qy);

        float p0 = pos[n*3+0], p1 = pos[n*3+1], p2 = pos[n*3+2];
        float x = r00*p0 + r01*p1 + r02*p2 + wt[0];
        float y = r10*p0 + r11*p1 + r12*p2 + wt[1];
        float z = r20*p0 + r21*p1 + r22*p2 + wt[2];

        float dnorm = sqrtf(x*x + y*y + z*z);
        bool  mask  = z > 1.1f;
        float zs    = mask ? z : 1.0f;
        float u     = x / zs;
        float v     = y / zs;
        mask = mask && (fabsf(u) < 0.64f) && (fabsf(v) < 0.64f);

        float iz  = 1.0f / zs;
        float iz2 = iz * iz;
        float xz2 = x * iz2, yz2 = y * iz2;
        float jw00 = iz*r00 - xz2*r20, jw01 = iz*r01 - xz2*r21, jw02 = iz*r02 - xz2*r22;
        float jw10 = iz*r10 - yz2*r20, jw11 = iz*r11 - yz2*r21, jw12 = iz*r12 - yz2*r22;

        float gw = quat[n*4+0], gx = quat[n*4+1], gy = quat[n*4+2], gz = quat[n*4+3];
        float gn = sqrtf(gw*gw + gx*gx + gy*gy + gz*gz) + 1e-12f;
        gw /= gn; gx /= gn; gy /= gn; gz /= gn;
        float g00 = 1.f - 2.f*(gy*gy + gz*gz), g01 = 2.f*(gx*gy - gw*gz), g02 = 2.f*(gx*gz + gw*gy);
        float g10 = 2.f*(gx*gy + gw*gz), g11 = 1.f - 2.f*(gx*gx + gz*gz), g12 = 2.f*(gy*gz - gw*gx);
        float g20 = 2.f*(gx*gz - gw*gy), g21 = 2.f*(gy*gz + gw*gx), g22 = 1.f - 2.f*(gx*gx + gy*gy);

        float sx = scale[n*3+0], sy = scale[n*3+1], sz = scale[n*3+2];
        float a00 = g00*sx, a01 = g01*sy, a02 = g02*sz;
        float a10 = g10*sx, a11 = g11*sy, a12 = g12*sz;
        float a20 = g20*sx, a21 = g21*sy, a22 = g22*sz;

        float c00 = a00*a00 + a01*a01 + a02*a02;
        float c01 = a00*a10 + a01*a11 + a02*a12;
        float c02 = a00*a20 + a01*a21 + a02*a22;
        float c11 = a10*a10 + a11*a11 + a12*a12;
        float c12 = a10*a20 + a11*a21 + a12*a22;
        float c22 = a20*a20 + a21*a21 + a22*a22;

        float t00 = c00*jw00 + c01*jw01 + c02*jw02;
        float t01 = c01*jw00 + c11*jw01 + c12*jw02;
        float t02 = c02*jw00 + c12*jw01 + c22*jw02;
        float t10 = c00*jw10 + c01*jw11 + c02*jw12;
        float t11 = c01*jw10 + c11*jw11 + c12*jw12;
        float t12 = c02*jw10 + c12*jw11 + c22*jw12;

        float a = jw00*t00 + jw01*t01 + jw02*t02 + 1e-6f;
        float bb= jw00*t10 + jw01*t11 + jw02*t12;
        float c = jw10*t10 + jw11*t11 + jw12*t12 + 1e-6f;

        float inv_det = 1.0f / fmaxf(a*c - bb*bb, 1e-12f);
        float A = c * inv_det;
        float B = bb * inv_det;
        float C = a * inv_det;

        g_rec0[n] = make_float4(u, v, -0.5f*A, -0.5f*C);
        g_recB[n] = B;
        g_rec1[n] = make_float4(mask ? opa[n] : 0.0f, rgb[n*3+0], rgb[n*3+1], rgb[n*3+2]);

        __half ruh = mask ? __float2half_ru(6.0f * sqrtf(a)) : __float2half(-1.0f);
        __half rvh = __float2half_ru(6.0f * sqrtf(c));
        __half2 rr = __halves2half2(ruh, rvh);
        g_cull[n] = make_float4(u, v, mask ? dnorm : INFINITY,
                                __uint_as_float(*(unsigned*)&rr));
    }
    __syncthreads();
    __threadfence();
    if (tid == 0) atomicAdd(&g_prep_done, 1);

    // ================= spin until all prep complete =========================
    if (tid == 0) { while (*((volatile int*)&g_prep_done) < NBLK) { } }
    __syncthreads();
    __threadfence();

    // ================= phase 2: per-tile cull (unsorted append) ============
    int tx = b & 7, ty = b >> 3;          // tile = 16x8 px
    float ulo = (tx*16 +  0.5f - 64.f) * 0.01f;
    float uhi = (tx*16 + 15.5f - 64.f) * 0.01f;
    float vlo = (ty*8  +  0.5f - 64.f) * 0.01f;
    float vhi = (ty*8  +  7.5f - 64.f) * 0.01f;

    __shared__ unsigned long long s_keys[NG];
    __shared__ unsigned long long s_sorted[NG];
    __shared__ int s_cnt;
    if (tid == 0) s_cnt = 0;
    __syncthreads();

    #pragma unroll
    for (int c = 0; c < NG / NTHR; c++) {
        int g = c * NTHR + tid;
        float4 cu = g_cull[g];
        unsigned hb = __float_as_uint(cu.w);
        float2 rad = __half22float2(*(__half2*)&hb);
        if (rad.x >= 0.f &&
            cu.x - rad.x <= uhi && cu.x + rad.x >= ulo &&
            cu.y - rad.y <= vhi && cu.y + rad.y >= vlo) {
            int p = atomicAdd(&s_cnt, 1);
            s_keys[p] = (((unsigned long long)__float_as_uint(cu.z)) << 32)
                      | (unsigned)g;
        }
    }
    __syncthreads();
    int cnt = s_cnt;

    // ================= phase 3: rank sort (keys unique) ====================
    for (int e = tid; e < cnt; e += NTHR) {
        unsigned long long k = s_keys[e];
        int r = 0;
        for (int j = 0; j < cnt; j++) r += (s_keys[j] < k);
        s_sorted[r] = k;
    }
    __syncthreads();

    // ================= phase 4: eight-segment front-to-back blend ==========
    __shared__ float4 t0[NTHR];
    __shared__ float  tB[NTHR];
    __shared__ float4 t1[NTHR];
    __shared__ float4 s_part[(NSEG-1) * PIXT];

    int seg = tid >> 7;             // 0..7
    int lt  = tid & (PIXT-1);       // pixel id within tile
    int segbase = (cnt * seg) >> 3;
    int segend  = (cnt * (seg+1)) >> 3;
    int seglen  = segend - segbase;

    int px = tx*16 + (lt & 15);
    int py = ty*8  + (lt >> 4);
    float pu = (px + 0.5f - 64.f) * 0.01f;
    float pv = (py + 0.5f - 64.f) * 0.01f;

    float T = 1.f, cr = 0.f, cg = 0.f, cb = 0.f;

    int rounds = (((cnt + 7) >> 3) + PIXT - 1) / PIXT;
    for (int r = 0; r < rounds; r++) {
        int off = r * PIXT;
        __syncthreads();
        if (off + lt < seglen) {
            int idx = (int)(s_sorted[segbase + off + lt] & 0xffffffffu);
            t0[tid] = g_rec0[idx];
            tB[tid] = g_recB[idx];
            t1[tid] = g_rec1[idx];
        }
        __syncthreads();
        int mlen = min(PIXT, seglen - off);
        int sb   = seg * PIXT;
        for (int i = 0; i < mlen; i++) {
            float4 a = t0[sb + i];
            float dx = pu - a.x;
            float dy = pv - a.y;
            float power = a.z*dx*dx + a.w*dy*dy + tB[sb + i]*dx*dy;
            // exp(-18)~1.5e-8 and saturated lanes (T<1e-5) contribute <1e-5 abs
            if (__any_sync(0xffffffffu, power > -18.0f && T > 1e-5f)) {
                float4 q = t1[sb + i];
                float al = fminf(q.x * __expf(fminf(power, 0.f)), 0.99f);
                float w  = T * al;
                cr = fmaf(w, q.y, cr);
                cg = fmaf(w, q.z, cg);
                cb = fmaf(w, q.w, cb);
                T -= w;
            }
        }
        if (__syncthreads_and(T < 1e-5f)) break;
    }

    // exact combine: c = c0 + T0*(c1 + T1*(... + T6*c7))
    __syncthreads();
    if (seg) s_part[(seg-1) * PIXT + lt] = make_float4(cr, cg, cb, T);
    __syncthreads();
    if (!seg) {
        float ccr = 0.f, ccg = 0.f, ccb = 0.f;
        // fold back-to-front over segments 7..1
        #pragma unroll
        for (int s = NSEG - 1; s >= 1; s--) {
            float4 ps = s_part[(s-1) * PIXT + lt];
            ccr = fmaf(ps.w, ccr, ps.x);
            ccg = fmaf(ps.w, ccg, ps.y);
            ccb = fmaf(ps.w, ccb, ps.z);
        }
        cr = fmaf(T, ccr, cr);
        cg = fmaf(T, ccg, cg);
        cb = fmaf(T, ccb, cb);
        int p = py * WW + px;
        out[p*3 + 0] = cr;
        out[p*3 + 1] = cg;
        out[p*3 + 2] = cb;
    }

    // ================= counter self-reset for next graph replay ============
    __syncthreads();
    if (tid == 0) {
        int o = atomicAdd(&g_fin_done, 1);
        if (o == NBLK - 1) {
            g_prep_done = 0;
            g_fin_done  = 0;
            __threadfence();
        }
    }
}

// ---------------------------------------------------------------------------
extern "C" void kernel_launch(void* const* d_in, const int* in_sizes, int n_in,
                              void* d_out, int out_size)
{
    const float* pos   = (const float*)d_in[0];
    const float* rgb   = (const float*)d_in[1];
    const float* opa   = (const float*)d_in[2];
    const float* quat  = (const float*)d_in[3];
    const float* scale = (const float*)d_in[4];
    const float* wq    = (const float*)d_in[5];
    const float* wt    = (const float*)d_in[6];
    float* out = (float*)d_out;

    splat_kernel<<<NBLK, NTHR>>>(pos, rgb, opa, quat, scale, wq, wt, out);
}